// round 8
// baseline (speedup 1.0000x reference)
#include <cuda_runtime.h>
#include <math.h>

#define N_ENT 200000
#define N_USR 100000
#define DIM   64
#define E_N   1500000
#define NI_N  1000000
#define N_RELM1 10
#define HALF_D 32   // float2 lanes per row
#define WPB  8      // warps per block
#define EBLK ((N_ENT + WPB - 1) / WPB)   // 25000
#define UBLK ((N_USR + WPB - 1) / WPB)   // 12500
#define ZBLK 512                          // cnt-rezero blocks appended to hop0 grid
#define NBINS (3 * N_ENT)                 // (head,virt) bins

// ---------------- device scratch (no allocation allowed) ----------------
// Invariant: g_cnt3 / g_cnt_usr are all-zero at entry to kernel_launch
// (zero-init at load; hop0 tail blocks re-zero after scatter each call).
__device__ int   g_cnt3[NBINS];
__device__ int   g_off3[NBINS + 1];
__device__ int   g_cnt_usr[N_USR];
__device__ int   g_off_usr[N_USR + 1];
__device__ int   g_packed[E_N];      // plain tail index (virt implied by segment)
__device__ int   g_items[NI_N];
__device__ float g_entB[N_ENT * DIM];
__device__ float g_usrB[N_USR * DIM];

// ---------------- helpers ----------------
__device__ __forceinline__ float wsum(float v) {
    #pragma unroll
    for (int o = 16; o > 0; o >>= 1) v += __shfl_xor_sync(0xffffffffu, v, o);
    return v;
}

__device__ __forceinline__ float2 squash_add(float2 acc, float den, float2 base) {
    float x = acc.x / den, y = acc.y / den;
    float sq = wsum(x * x + y * y);
    float nrm = sqrtf(sq);
    float s = (sq / (sq + 1.0f)) / fmaxf(nrm, 1e-12f);
    return make_float2(x * s + base.x, y * s + base.y);
}

// per-block relation->virt remap into smem (cheap: 30 dot products)
__device__ __forceinline__ void compute_remap_smem(const float* __restrict__ relw,
                                                   const float* __restrict__ lat,
                                                   int* s_remap, float* s_dot) {
    int t = threadIdx.x;
    if (t < 3 * N_RELM1) {
        int r = t / 3, v = t % 3;
        float s = 0.f;
        for (int k = 0; k < DIM; k++) s += relw[r * DIM + k] * lat[v * DIM + k];
        s_dot[t] = s;
    }
    __syncthreads();
    if (t < N_RELM1) {
        float b = s_dot[t * 3]; int bi = 0;
        if (s_dot[t * 3 + 1] > b) { b = s_dot[t * 3 + 1]; bi = 1; }
        if (s_dot[t * 3 + 2] > b) { b = s_dot[t * 3 + 2]; bi = 2; }
        s_remap[t] = bi;
    }
    __syncthreads();
}

// ---------------- preprocessing (3 launches) ----------------

// L0: histogram (head,virt) bins + user bins
__global__ void __launch_bounds__(256)
hist3_k(const int* __restrict__ heads, const int* __restrict__ et,
        const int* __restrict__ uidx,
        const float* __restrict__ relw, const float* __restrict__ lat) {
    __shared__ int s_remap[16];
    __shared__ float s_dot[32];
    compute_remap_smem(relw, lat, s_remap, s_dot);
    int total = E_N + NI_N;
    for (int i = blockIdx.x * blockDim.x + threadIdx.x; i < total; i += gridDim.x * blockDim.x) {
        if (i < E_N) atomicAdd(&g_cnt3[heads[i] * 3 + s_remap[et[i] - 1]], 1);
        else         atomicAdd(&g_cnt_usr[uidx[i - E_N]], 1);
    }
}

// L1: one block per array — exclusive scan (4 elems/thread), re-zero cnt
__global__ void __launch_bounds__(1024) scan_both_k() {
    int *cnt, *off; int n;
    if (blockIdx.x == 0) { cnt = g_cnt3; off = g_off3; n = NBINS; }
    else                 { cnt = g_cnt_usr; off = g_off_usr; n = N_USR; }
    const int tid = threadIdx.x;
    const int lane = tid & 31, wid = tid >> 5;
    __shared__ int wsh[32];
    __shared__ int carry_s;
    if (tid == 0) carry_s = 0;
    __syncthreads();
    for (int base = 0; base < n; base += 4096) {
        int i0 = base + tid * 4;
        int a0 = 0, a1 = 0, a2 = 0, a3 = 0;
        if (i0 < n) { a0 = cnt[i0]; a1 = cnt[i0 + 1]; a2 = cnt[i0 + 2]; a3 = cnt[i0 + 3]; }
        int tsum = a0 + a1 + a2 + a3;
        int x = tsum;
        #pragma unroll
        for (int o = 1; o < 32; o <<= 1) {
            int t = __shfl_up_sync(0xffffffffu, x, o);
            if (lane >= o) x += t;
        }
        if (lane == 31) wsh[wid] = x;
        __syncthreads();
        if (wid == 0) {
            int y = wsh[lane];
            #pragma unroll
            for (int o = 1; o < 32; o <<= 1) {
                int t = __shfl_up_sync(0xffffffffu, y, o);
                if (lane >= o) y += t;
            }
            wsh[lane] = y;
        }
        __syncthreads();
        int woff = (wid > 0) ? wsh[wid - 1] : 0;
        int incl = x + woff;
        int carry = carry_s;
        if (i0 < n) {
            int ex = carry + incl - tsum;
            off[i0]     = ex;
            off[i0 + 1] = ex + a0;
            off[i0 + 2] = ex + a0 + a1;
            off[i0 + 3] = ex + a0 + a1 + a2;
            cnt[i0] = 0; cnt[i0 + 1] = 0; cnt[i0 + 2] = 0; cnt[i0 + 3] = 0;
        }
        __syncthreads();
        if (tid == 1023) carry_s = carry + incl;
        __syncthreads();
    }
    if (tid == 0) off[n] = carry_s;
}

// L2: scatter tails into virt-sorted CSR; user items into CSR
__global__ void __launch_bounds__(256)
scatter3_k(const int* __restrict__ heads, const int* __restrict__ tails,
           const int* __restrict__ et,
           const int* __restrict__ uidx, const int* __restrict__ iidx,
           const float* __restrict__ relw, const float* __restrict__ lat) {
    __shared__ int s_remap[16];
    __shared__ float s_dot[32];
    compute_remap_smem(relw, lat, s_remap, s_dot);
    int total = E_N + NI_N;
    for (int i = blockIdx.x * blockDim.x + threadIdx.x; i < total; i += gridDim.x * blockDim.x) {
        if (i < E_N) {
            int key = heads[i] * 3 + s_remap[et[i] - 1];
            int pos = g_off3[key] + atomicAdd(&g_cnt3[key], 1);
            g_packed[pos] = tails[i];
        } else {
            int k = i - E_N;
            int u = uidx[k];
            int pos = g_off_usr[u] + atomicAdd(&g_cnt_usr[u], 1);
            g_items[pos] = iidx[k];
        }
    }
}

// ---------------- fused hop kernel (virt-sorted segments) ----------------
__global__ void __launch_bounds__(256)
fused_hop_k(const float2* __restrict__ ent_in, const float2* __restrict__ usr_in,
            const float* __restrict__ aggw, int hop, int init,
            const int* __restrict__ off3, const int* __restrict__ packed,
            const int* __restrict__ off_u, const int* __restrict__ items,
            float2* __restrict__ ent_store, float2* __restrict__ usr_store,
            float2* __restrict__ res_ent, float2* __restrict__ res_usr)
{
    __shared__ float s_d[WPB][32];     // pass-1 dots for first 32 edges of each head

    const int wid  = threadIdx.x >> 5;
    const int lane = threadIdx.x & 31;
    float* __restrict__ sd = s_d[wid];

    if (blockIdx.x >= EBLK + UBLK) {
        // cnt re-zero duty (hop0 only): restore all-zero invariant
        int i = (blockIdx.x - (EBLK + UBLK)) * 256 + threadIdx.x;
        for (; i < NBINS + N_USR; i += ZBLK * 256) {
            if (i < NBINS) g_cnt3[i] = 0;
            else           g_cnt_usr[i - NBINS] = 0;
        }
        return;
    }

    if (blockIdx.x < EBLK) {
        // ======================= ENTITY =======================
        int w = blockIdx.x * WPB + wid;
        if (w >= N_ENT) return;

        float2 en = ent_in[w * HALF_D + lane];
        int s0 = off3[3 * w], s1 = off3[3 * w + 1], s2 = off3[3 * w + 2], s3 = off3[3 * w + 3];
        int seg[4] = {s0, s1, s2, s3};
        float den[3];
        den[0] = fmaxf((float)(s1 - s0), 1.f);
        den[1] = fmaxf((float)(s2 - s1), 1.f);
        den[2] = fmaxf((float)(s3 - s2), 1.f);

        float a0 = aggw[hop * 3 + 0], a1 = aggw[hop * 3 + 1], a2 = aggw[hop * 3 + 2];
        float mx = fmaxf(a0, fmaxf(a1, a2));
        float e0 = expf(a0 - mx), e1 = expf(a1 - mx), e2 = expf(a2 - mx);
        float inv = 1.0f / (e0 + e1 + e2);
        float w0 = e0 * inv, w1 = e1 * inv, w2 = e2 * inv;

        // ---- pass 0: plain per-segment sums (no dispatch, no counting) ----
        float2 U1[3];
        #pragma unroll
        for (int v = 0; v < 3; v++) {
            float2 A = {0, 0};
            for (int b = seg[v]; b < seg[v + 1]; b += 32) {
                int m = min(32, seg[v + 1] - b);
                int pk = (lane < m) ? packed[b + lane] : 0;
                for (int j = 0; j < m; j++) {
                    int t = __shfl_sync(0xffffffffu, pk, j);
                    float2 nt = ent_in[t * HALF_D + lane];
                    A.x += nt.x; A.y += nt.y;
                }
            }
            U1[v] = squash_add(A, den[v], en);
        }

        // ---- pass 1: sim-weighted; cache dots for first 32 edges of head ----
        float2 U2[3];
        #pragma unroll
        for (int v = 0; v < 3; v++) {
            float2 A = {0, 0};
            for (int b = seg[v]; b < seg[v + 1]; b += 32) {
                int m = min(32, seg[v + 1] - b);
                int pk = (lane < m) ? packed[b + lane] : 0;
                for (int j = 0; j < m; j++) {
                    int t = __shfl_sync(0xffffffffu, pk, j);
                    float2 nt = ent_in[t * HALF_D + lane];
                    float d = wsum(U1[v].x * nt.x + U1[v].y * nt.y);
                    int idx = b + j - s0;
                    if (idx < 32 && lane == 0) sd[idx] = d;
                    A.x += d * nt.x; A.y += d * nt.y;
                }
            }
            U2[v] = squash_add(A, den[v], en);
        }

        __syncwarp();

        // ---- pass 2: scale = d1^2 * d2 (d1 from sd cache) ----
        float2 U3[3];
        #pragma unroll
        for (int v = 0; v < 3; v++) {
            float2 A = {0, 0};
            for (int b = seg[v]; b < seg[v + 1]; b += 32) {
                int m = min(32, seg[v + 1] - b);
                int pk = (lane < m) ? packed[b + lane] : 0;
                for (int j = 0; j < m; j++) {
                    int t = __shfl_sync(0xffffffffu, pk, j);
                    float2 nt = ent_in[t * HALF_D + lane];
                    float pb = U2[v].x * nt.x + U2[v].y * nt.y;
                    int idx = b + j - s0;
                    float pa;
                    if (idx < 32) {
                        pb = wsum(pb);
                        pa = sd[idx];
                    } else {                       // ultra-rare deep tail
                        pa = U1[v].x * nt.x + U1[v].y * nt.y;
                        #pragma unroll
                        for (int o = 16; o > 0; o >>= 1) {
                            pa += __shfl_xor_sync(0xffffffffu, pa, o);
                            pb += __shfl_xor_sync(0xffffffffu, pb, o);
                        }
                    }
                    float sc = pa * pa * pb;
                    A.x += sc * nt.x; A.y += sc * nt.y;
                }
            }
            U3[v] = make_float2(A.x / den[v] + en.x, A.y / den[v] + en.y);
        }

        float2 ag = make_float2(w0 * U3[0].x + w1 * U3[1].x + w2 * U3[2].x,
                                w0 * U3[0].y + w1 * U3[1].y + w2 * U3[2].y);
        float sq = wsum(ag.x * ag.x + ag.y * ag.y);
        float in2 = 1.0f / fmaxf(sqrtf(sq), 1e-12f);
        float2 o = make_float2(ag.x * in2, ag.y * in2);
        if (ent_store) ent_store[w * HALF_D + lane] = o;
        float2 r;
        if (init) { r.x = en.x + o.x; r.y = en.y + o.y; }
        else { r = res_ent[w * HALF_D + lane]; r.x += o.x; r.y += o.y; }
        res_ent[w * HALF_D + lane] = r;

    } else {
        // ======================= USER =======================
        int w = (blockIdx.x - EBLK) * WPB + wid;
        if (w >= N_USR) return;

        float2 un = usr_in[w * HALF_D + lane];
        int s = off_u[w], e = off_u[w + 1];
        float den = fmaxf((float)(e - s), 1.f);

        // it0
        float2 A = {0, 0};
        for (int b = s; b < e; b += 32) {
            int m = min(32, e - b);
            int it = (lane < m) ? items[b + lane] : 0;
            for (int j = 0; j < m; j++) {
                int t = __shfl_sync(0xffffffffu, it, j);
                float2 nt = ent_in[t * HALF_D + lane];
                A.x += nt.x; A.y += nt.y;
            }
        }
        float2 u1 = squash_add(A, den, un);

        // it1
        A = make_float2(0, 0);
        for (int b = s; b < e; b += 32) {
            int m = min(32, e - b);
            int it = (lane < m) ? items[b + lane] : 0;
            for (int j = 0; j < m; j++) {
                int t = __shfl_sync(0xffffffffu, it, j);
                float2 nt = ent_in[t * HALF_D + lane];
                float d = wsum(u1.x * nt.x + u1.y * nt.y);
                A.x += d * nt.x; A.y += d * nt.y;
            }
        }
        float2 u2 = squash_add(A, den, un);

        // it2 (no squash)
        A = make_float2(0, 0);
        for (int b = s; b < e; b += 32) {
            int m = min(32, e - b);
            int it = (lane < m) ? items[b + lane] : 0;
            for (int j = 0; j < m; j++) {
                int t = __shfl_sync(0xffffffffu, it, j);
                float2 nt = ent_in[t * HALF_D + lane];
                float d = wsum(u2.x * nt.x + u2.y * nt.y);
                A.x += d * nt.x; A.y += d * nt.y;
            }
        }
        float2 u3 = make_float2(A.x / den + un.x, A.y / den + un.y);

        float sq = wsum(u3.x * u3.x + u3.y * u3.y);
        float in2 = 1.0f / fmaxf(sqrtf(sq), 1e-12f);
        float2 o = make_float2(u3.x * in2, u3.y * in2);
        if (usr_store) usr_store[w * HALF_D + lane] = o;
        float2 r;
        if (init) { r.x = un.x + o.x; r.y = un.y + o.y; }
        else { r = res_usr[w * HALF_D + lane]; r.x += o.x; r.y += o.y; }
        res_usr[w * HALF_D + lane] = r;
    }
}

// ---------------- launch (5 launches; hop0 is launch #3 → ncu -s 5 hits it) ----------------
extern "C" void kernel_launch(void* const* d_in, const int* in_sizes, int n_in,
                              void* d_out, int out_size) {
    const float* entity_emb = (const float*)d_in[0];
    const float* user_emb   = (const float*)d_in[1];
    const float* latent     = (const float*)d_in[2];
    const float* relw       = (const float*)d_in[3];
    const float* aggw       = (const float*)d_in[4];
    const int*   eidx       = (const int*)d_in[5];   // [2,E]: head row, then tail row
    const int*   etype      = (const int*)d_in[6];
    const int*   uidx       = (const int*)d_in[7];
    const int*   iidx       = (const int*)d_in[8];
    float* out = (float*)d_out;

    int *p_off3, *p_off_usr, *p_packed, *p_items;
    float *p_entB, *p_usrB;
    cudaGetSymbolAddress((void**)&p_off3,    g_off3);
    cudaGetSymbolAddress((void**)&p_off_usr, g_off_usr);
    cudaGetSymbolAddress((void**)&p_packed,  g_packed);
    cudaGetSymbolAddress((void**)&p_items,   g_items);
    cudaGetSymbolAddress((void**)&p_entB,    g_entB);
    cudaGetSymbolAddress((void**)&p_usrB,    g_usrB);

    hist3_k<<<2048, 256>>>(eidx, etype, uidx, relw, latent);                        // #0
    scan_both_k<<<2, 1024>>>();                                                     // #1
    scatter3_k<<<2048, 256>>>(eidx, eidx + E_N, etype, uidx, iidx, relw, latent);   // #2

    float2* res_e = (float2*)out;
    float2* res_u = (float2*)(out + (size_t)N_ENT * DIM);

    // hop 0 (#3): base embeddings in; init residual; ZBLK tail blocks re-zero cnt
    fused_hop_k<<<EBLK + UBLK + ZBLK, 256>>>(
        (const float2*)entity_emb, (const float2*)user_emb, aggw, 0, 1,
        p_off3, p_packed, p_off_usr, p_items,
        (float2*)p_entB, (float2*)p_usrB, res_e, res_u);

    // hop 1 (#4): hop-0 outputs in; accumulate residual only
    fused_hop_k<<<EBLK + UBLK, 256>>>(
        (const float2*)p_entB, (const float2*)p_usrB, aggw, 1, 0,
        p_off3, p_packed, p_off_usr, p_items,
        nullptr, nullptr, res_e, res_u);
}

// round 9
// speedup vs baseline: 1.5479x; 1.5479x over previous
#include <cuda_runtime.h>
#include <math.h>

#define N_ENT 200000
#define N_USR 100000
#define DIM   64
#define E_N   1500000
#define NI_N  1000000
#define N_RELM1 10
#define HALF_D 32   // float2 lanes per row
#define WPB  8      // warps per block
#define EBLK ((N_ENT + WPB - 1) / WPB)   // 25000
#define UBLK ((N_USR + WPB - 1) / WPB)   // 12500
#define ZBLK 512                          // cnt-rezero blocks appended to hop0 grid

// ---------------- device scratch (no allocation allowed) ----------------
// Invariant: g_cnt_* are all-zero at entry to kernel_launch (zero-init at load;
// hop0 tail blocks re-zero them after scatter each call).
__device__ int   g_remap[16];
__device__ int   g_cnt_ent[N_ENT];
__device__ int   g_off_ent[N_ENT + 1];
__device__ int   g_cnt_usr[N_USR];
__device__ int   g_off_usr[N_USR + 1];
__device__ int   g_packed[E_N];      // tail | (virt<<18)
__device__ int   g_items[NI_N];
__device__ float g_entB[N_ENT * DIM];
__device__ float g_usrB[N_USR * DIM];

// ---------------- helpers ----------------
__device__ __forceinline__ float wsum(float v) {
    #pragma unroll
    for (int o = 16; o > 0; o >>= 1) v += __shfl_xor_sync(0xffffffffu, v, o);
    return v;
}

// squash(acc*inv) + base, with precomputed reciprocal and one fast divide
__device__ __forceinline__ float2 squash_addi(float2 acc, float inv, float2 base) {
    float x = acc.x * inv, y = acc.y * inv;
    float sq = wsum(x * x + y * y);
    float s = __fdividef(sq, (sq + 1.0f) * fmaxf(sqrtf(sq), 1e-12f));
    return make_float2(x * s + base.x, y * s + base.y);
}

// ---------------- preprocessing (3 launches) ----------------

// L0: histogram heads + users; first 10 threads also compute relation remap.
__global__ void __launch_bounds__(256)
hist_both_k(const int* __restrict__ heads, const int* __restrict__ uidx,
            const float* __restrict__ relw, const float* __restrict__ lat) {
    int gi = blockIdx.x * blockDim.x + threadIdx.x;
    if (gi < N_RELM1) {
        float best = -1e30f; int bi = 0;
        for (int v = 0; v < 3; v++) {
            float sdot = 0.f;
            #pragma unroll 1
            for (int k = 0; k < DIM; k++) sdot += relw[gi * DIM + k] * lat[v * DIM + k];
            if (sdot > best) { best = sdot; bi = v; }
        }
        g_remap[gi] = bi;
    }
    int total = E_N + NI_N;
    for (int i = gi; i < total; i += gridDim.x * blockDim.x) {
        if (i < E_N) atomicAdd(&g_cnt_ent[heads[i]], 1);
        else         atomicAdd(&g_cnt_usr[uidx[i - E_N]], 1);
    }
}

// L1: one block per array — exclusive scan into off[], re-zero cnt[]
__global__ void __launch_bounds__(1024) scan_both_k() {
    int *cnt, *off; int n;
    if (blockIdx.x == 0) { cnt = g_cnt_ent; off = g_off_ent; n = N_ENT; }
    else                 { cnt = g_cnt_usr; off = g_off_usr; n = N_USR; }
    const int tid = threadIdx.x;
    const int lane = tid & 31, wid = tid >> 5;
    __shared__ int wsh[32];
    __shared__ int carry_s;
    if (tid == 0) carry_s = 0;
    __syncthreads();
    for (int base = 0; base < n; base += 1024) {
        int i = base + tid;
        int v = (i < n) ? cnt[i] : 0;
        int x = v;
        #pragma unroll
        for (int o = 1; o < 32; o <<= 1) {
            int t = __shfl_up_sync(0xffffffffu, x, o);
            if (lane >= o) x += t;
        }
        if (lane == 31) wsh[wid] = x;
        __syncthreads();
        if (wid == 0) {
            int y = wsh[lane];
            #pragma unroll
            for (int o = 1; o < 32; o <<= 1) {
                int t = __shfl_up_sync(0xffffffffu, y, o);
                if (lane >= o) y += t;
            }
            wsh[lane] = y;
        }
        __syncthreads();
        int warp_off = (wid > 0) ? wsh[wid - 1] : 0;
        int incl = x + warp_off;
        int carry = carry_s;
        if (i < n) { off[i] = carry + incl - v; cnt[i] = 0; }
        __syncthreads();
        if (tid == 1023) carry_s = carry + incl;
        __syncthreads();
    }
    if (tid == 0) off[n] = carry_s;
}

// L2: scatter edges (packed tail|virt) and user items into CSR order
__global__ void __launch_bounds__(256)
scatter_both_k(const int* __restrict__ heads, const int* __restrict__ tails,
               const int* __restrict__ et,
               const int* __restrict__ uidx, const int* __restrict__ iidx) {
    int total = E_N + NI_N;
    for (int i = blockIdx.x * blockDim.x + threadIdx.x; i < total; i += gridDim.x * blockDim.x) {
        if (i < E_N) {
            int h = heads[i];
            int pos = g_off_ent[h] + atomicAdd(&g_cnt_ent[h], 1);
            int v = g_remap[et[i] - 1];
            g_packed[pos] = tails[i] | (v << 18);
        } else {
            int k = i - E_N;
            int u = uidx[k];
            int pos = g_off_usr[u] + atomicAdd(&g_cnt_usr[u], 1);
            g_items[pos] = iidx[k];
        }
    }
}

// ---------------- fused hop kernel ----------------
__global__ void __launch_bounds__(256)
fused_hop_k(const float2* __restrict__ ent_in, const float2* __restrict__ usr_in,
            const float* __restrict__ aggw, int hop, int init,
            const int* __restrict__ off_e, const int* __restrict__ packed,
            const int* __restrict__ off_u, const int* __restrict__ items,
            float2* __restrict__ ent_store, float2* __restrict__ usr_store,
            float2* __restrict__ res_ent, float2* __restrict__ res_usr)
{
    __shared__ float s_d[WPB][32];     // pass-1 dots, first 32 edges per head

    const int wid  = threadIdx.x >> 5;
    const int lane = threadIdx.x & 31;
    float* __restrict__ sd = s_d[wid];

    if (blockIdx.x >= EBLK + UBLK) {
        // cnt re-zero duty (hop0 only): restore the all-zero invariant
        int i = (blockIdx.x - (EBLK + UBLK)) * 256 + threadIdx.x;
        for (; i < N_ENT + N_USR; i += ZBLK * 256) {
            if (i < N_ENT) g_cnt_ent[i] = 0;
            else           g_cnt_usr[i - N_ENT] = 0;
        }
        return;
    }

    if (blockIdx.x < EBLK) {
        // ======================= ENTITY =======================
        int w = blockIdx.x * WPB + wid;
        if (w >= N_ENT) return;

        float2 en = ent_in[w * HALF_D + lane];
        int s = off_e[w], e = off_e[w + 1];
        int deg = e - s;

        float a0 = aggw[hop * 3 + 0], a1 = aggw[hop * 3 + 1], a2 = aggw[hop * 3 + 2];
        float mx = fmaxf(a0, fmaxf(a1, a2));
        float e0 = __expf(a0 - mx), e1 = __expf(a1 - mx), e2 = __expf(a2 - mx);
        float inv = __fdividef(1.0f, e0 + e1 + e2);
        float w0 = e0 * inv, w1 = e1 * inv, w2 = e2 * inv;

        float2 u30, u31, u32;

        if (deg <= 32) {
            // ---------- fast path: edge list resident in one register ----------
            int pk = (lane < deg) ? packed[s + lane] : 0;

            // pass 0: plain per-virt sums
            float2 A0 = {0, 0}, A1 = {0, 0}, A2 = {0, 0};
            int c0 = 0, c1 = 0, c2 = 0;
            for (int j = 0; j < deg; j++) {
                int p = __shfl_sync(0xffffffffu, pk, j);
                int t = p & 0x3FFFF, v = p >> 18;
                float2 nt = ent_in[t * HALF_D + lane];
                if (v == 0)      { A0.x += nt.x; A0.y += nt.y; c0++; }
                else if (v == 1) { A1.x += nt.x; A1.y += nt.y; c1++; }
                else             { A2.x += nt.x; A2.y += nt.y; c2++; }
            }
            float i0 = __fdividef(1.f, fmaxf((float)c0, 1.f));
            float i1 = __fdividef(1.f, fmaxf((float)c1, 1.f));
            float i2 = __fdividef(1.f, fmaxf((float)c2, 1.f));
            float2 u10 = squash_addi(A0, i0, en);
            float2 u11 = squash_addi(A1, i1, en);
            float2 u12 = squash_addi(A2, i2, en);

            // pass 1: sim-weighted; cache dots in sd
            A0 = make_float2(0, 0); A1 = make_float2(0, 0); A2 = make_float2(0, 0);
            for (int j = 0; j < deg; j++) {
                int p = __shfl_sync(0xffffffffu, pk, j);
                int t = p & 0x3FFFF, v = p >> 18;
                float2 nt = ent_in[t * HALF_D + lane];
                float2 uv = (v == 0) ? u10 : ((v == 1) ? u11 : u12);
                float d = wsum(uv.x * nt.x + uv.y * nt.y);
                if (lane == 0) sd[j] = d;
                if (v == 0)      { A0.x += d * nt.x; A0.y += d * nt.y; }
                else if (v == 1) { A1.x += d * nt.x; A1.y += d * nt.y; }
                else             { A2.x += d * nt.x; A2.y += d * nt.y; }
            }
            float2 u20 = squash_addi(A0, i0, en);
            float2 u21 = squash_addi(A1, i1, en);
            float2 u22 = squash_addi(A2, i2, en);

            __syncwarp();

            // pass 2: scale = d1^2 * d2 (d1 from sd)
            A0 = make_float2(0, 0); A1 = make_float2(0, 0); A2 = make_float2(0, 0);
            for (int j = 0; j < deg; j++) {
                int p = __shfl_sync(0xffffffffu, pk, j);
                int t = p & 0x3FFFF, v = p >> 18;
                float2 nt = ent_in[t * HALF_D + lane];
                float2 uB = (v == 0) ? u20 : ((v == 1) ? u21 : u22);
                float pb = wsum(uB.x * nt.x + uB.y * nt.y);
                float pa = sd[j];
                float sc = pa * pa * pb;
                if (v == 0)      { A0.x += sc * nt.x; A0.y += sc * nt.y; }
                else if (v == 1) { A1.x += sc * nt.x; A1.y += sc * nt.y; }
                else             { A2.x += sc * nt.x; A2.y += sc * nt.y; }
            }
            u30 = make_float2(A0.x * i0 + en.x, A0.y * i0 + en.y);
            u31 = make_float2(A1.x * i1 + en.x, A1.y * i1 + en.y);
            u32 = make_float2(A2.x * i2 + en.x, A2.y * i2 + en.y);
        } else {
            // ---------- generic path (rare deg > 32) ----------
            float2 A0 = {0, 0}, A1 = {0, 0}, A2 = {0, 0};
            int c0 = 0, c1 = 0, c2 = 0;
            for (int b = s; b < e; b += 32) {
                int m = min(32, e - b);
                int pk = (lane < m) ? packed[b + lane] : 0;
                for (int j = 0; j < m; j++) {
                    int p = __shfl_sync(0xffffffffu, pk, j);
                    int t = p & 0x3FFFF, v = p >> 18;
                    float2 nt = ent_in[t * HALF_D + lane];
                    if (v == 0)      { A0.x += nt.x; A0.y += nt.y; c0++; }
                    else if (v == 1) { A1.x += nt.x; A1.y += nt.y; c1++; }
                    else             { A2.x += nt.x; A2.y += nt.y; c2++; }
                }
            }
            float i0 = __fdividef(1.f, fmaxf((float)c0, 1.f));
            float i1 = __fdividef(1.f, fmaxf((float)c1, 1.f));
            float i2 = __fdividef(1.f, fmaxf((float)c2, 1.f));
            float2 u10 = squash_addi(A0, i0, en);
            float2 u11 = squash_addi(A1, i1, en);
            float2 u12 = squash_addi(A2, i2, en);

            A0 = make_float2(0, 0); A1 = make_float2(0, 0); A2 = make_float2(0, 0);
            for (int b = s; b < e; b += 32) {
                int m = min(32, e - b);
                int pk = (lane < m) ? packed[b + lane] : 0;
                for (int j = 0; j < m; j++) {
                    int p = __shfl_sync(0xffffffffu, pk, j);
                    int t = p & 0x3FFFF, v = p >> 18;
                    float2 nt = ent_in[t * HALF_D + lane];
                    float2 uv = (v == 0) ? u10 : ((v == 1) ? u11 : u12);
                    float d = wsum(uv.x * nt.x + uv.y * nt.y);
                    if (v == 0)      { A0.x += d * nt.x; A0.y += d * nt.y; }
                    else if (v == 1) { A1.x += d * nt.x; A1.y += d * nt.y; }
                    else             { A2.x += d * nt.x; A2.y += d * nt.y; }
                }
            }
            float2 u20 = squash_addi(A0, i0, en);
            float2 u21 = squash_addi(A1, i1, en);
            float2 u22 = squash_addi(A2, i2, en);

            A0 = make_float2(0, 0); A1 = make_float2(0, 0); A2 = make_float2(0, 0);
            for (int b = s; b < e; b += 32) {
                int m = min(32, e - b);
                int pk = (lane < m) ? packed[b + lane] : 0;
                for (int j = 0; j < m; j++) {
                    int p = __shfl_sync(0xffffffffu, pk, j);
                    int t = p & 0x3FFFF, v = p >> 18;
                    float2 nt = ent_in[t * HALF_D + lane];
                    float2 uA = (v == 0) ? u10 : ((v == 1) ? u11 : u12);
                    float2 uB = (v == 0) ? u20 : ((v == 1) ? u21 : u22);
                    float pa = uA.x * nt.x + uA.y * nt.y;
                    float pb = uB.x * nt.x + uB.y * nt.y;
                    #pragma unroll
                    for (int o = 16; o > 0; o >>= 1) {
                        pa += __shfl_xor_sync(0xffffffffu, pa, o);
                        pb += __shfl_xor_sync(0xffffffffu, pb, o);
                    }
                    float sc = pa * pa * pb;
                    if (v == 0)      { A0.x += sc * nt.x; A0.y += sc * nt.y; }
                    else if (v == 1) { A1.x += sc * nt.x; A1.y += sc * nt.y; }
                    else             { A2.x += sc * nt.x; A2.y += sc * nt.y; }
                }
            }
            u30 = make_float2(A0.x * i0 + en.x, A0.y * i0 + en.y);
            u31 = make_float2(A1.x * i1 + en.x, A1.y * i1 + en.y);
            u32 = make_float2(A2.x * i2 + en.x, A2.y * i2 + en.y);
        }

        // weighted agg + l2norm + residual
        float2 ag = make_float2(w0 * u30.x + w1 * u31.x + w2 * u32.x,
                                w0 * u30.y + w1 * u31.y + w2 * u32.y);
        float sq = wsum(ag.x * ag.x + ag.y * ag.y);
        float in2 = __fdividef(1.0f, fmaxf(sqrtf(sq), 1e-12f));
        float2 o = make_float2(ag.x * in2, ag.y * in2);
        if (ent_store) ent_store[w * HALF_D + lane] = o;
        float2 r;
        if (init) { r.x = en.x + o.x; r.y = en.y + o.y; }
        else { r = res_ent[w * HALF_D + lane]; r.x += o.x; r.y += o.y; }
        res_ent[w * HALF_D + lane] = r;

    } else {
        // ======================= USER =======================
        int w = (blockIdx.x - EBLK) * WPB + wid;
        if (w >= N_USR) return;

        float2 un = usr_in[w * HALF_D + lane];
        int s = off_u[w], e = off_u[w + 1];
        int deg = e - s;
        float invd = __fdividef(1.f, fmaxf((float)deg, 1.f));
        float2 u3;

        if (deg <= 32) {
            // ---------- fast path ----------
            int it = (lane < deg) ? items[s + lane] : 0;

            float2 A = {0, 0};
            for (int j = 0; j < deg; j++) {
                int t = __shfl_sync(0xffffffffu, it, j);
                float2 nt = ent_in[t * HALF_D + lane];
                A.x += nt.x; A.y += nt.y;
            }
            float2 u1 = squash_addi(A, invd, un);

            A = make_float2(0, 0);
            for (int j = 0; j < deg; j++) {
                int t = __shfl_sync(0xffffffffu, it, j);
                float2 nt = ent_in[t * HALF_D + lane];
                float d = wsum(u1.x * nt.x + u1.y * nt.y);
                A.x += d * nt.x; A.y += d * nt.y;
            }
            float2 u2 = squash_addi(A, invd, un);

            A = make_float2(0, 0);
            for (int j = 0; j < deg; j++) {
                int t = __shfl_sync(0xffffffffu, it, j);
                float2 nt = ent_in[t * HALF_D + lane];
                float d = wsum(u2.x * nt.x + u2.y * nt.y);
                A.x += d * nt.x; A.y += d * nt.y;
            }
            u3 = make_float2(A.x * invd + un.x, A.y * invd + un.y);
        } else {
            // ---------- generic path (rare) ----------
            float2 A = {0, 0};
            for (int b = s; b < e; b += 32) {
                int m = min(32, e - b);
                int it = (lane < m) ? items[b + lane] : 0;
                for (int j = 0; j < m; j++) {
                    int t = __shfl_sync(0xffffffffu, it, j);
                    float2 nt = ent_in[t * HALF_D + lane];
                    A.x += nt.x; A.y += nt.y;
                }
            }
            float2 u1 = squash_addi(A, invd, un);

            A = make_float2(0, 0);
            for (int b = s; b < e; b += 32) {
                int m = min(32, e - b);
                int it = (lane < m) ? items[b + lane] : 0;
                for (int j = 0; j < m; j++) {
                    int t = __shfl_sync(0xffffffffu, it, j);
                    float2 nt = ent_in[t * HALF_D + lane];
                    float d = wsum(u1.x * nt.x + u1.y * nt.y);
                    A.x += d * nt.x; A.y += d * nt.y;
                }
            }
            float2 u2 = squash_addi(A, invd, un);

            A = make_float2(0, 0);
            for (int b = s; b < e; b += 32) {
                int m = min(32, e - b);
                int it = (lane < m) ? items[b + lane] : 0;
                for (int j = 0; j < m; j++) {
                    int t = __shfl_sync(0xffffffffu, it, j);
                    float2 nt = ent_in[t * HALF_D + lane];
                    float d = wsum(u2.x * nt.x + u2.y * nt.y);
                    A.x += d * nt.x; A.y += d * nt.y;
                }
            }
            u3 = make_float2(A.x * invd + un.x, A.y * invd + un.y);
        }

        float sq = wsum(u3.x * u3.x + u3.y * u3.y);
        float in2 = __fdividef(1.0f, fmaxf(sqrtf(sq), 1e-12f));
        float2 o = make_float2(u3.x * in2, u3.y * in2);
        if (usr_store) usr_store[w * HALF_D + lane] = o;
        float2 r;
        if (init) { r.x = un.x + o.x; r.y = un.y + o.y; }
        else { r = res_usr[w * HALF_D + lane]; r.x += o.x; r.y += o.y; }
        res_usr[w * HALF_D + lane] = r;
    }
}

// ---------------- launch (5 launches) ----------------
extern "C" void kernel_launch(void* const* d_in, const int* in_sizes, int n_in,
                              void* d_out, int out_size) {
    const float* entity_emb = (const float*)d_in[0];
    const float* user_emb   = (const float*)d_in[1];
    const float* latent     = (const float*)d_in[2];
    const float* relw       = (const float*)d_in[3];
    const float* aggw       = (const float*)d_in[4];
    const int*   eidx       = (const int*)d_in[5];   // [2,E]: head row, then tail row
    const int*   etype      = (const int*)d_in[6];
    const int*   uidx       = (const int*)d_in[7];
    const int*   iidx       = (const int*)d_in[8];
    float* out = (float*)d_out;

    int *p_off_ent, *p_off_usr, *p_packed, *p_items;
    float *p_entB, *p_usrB;
    cudaGetSymbolAddress((void**)&p_off_ent, g_off_ent);
    cudaGetSymbolAddress((void**)&p_off_usr, g_off_usr);
    cudaGetSymbolAddress((void**)&p_packed,  g_packed);
    cudaGetSymbolAddress((void**)&p_items,   g_items);
    cudaGetSymbolAddress((void**)&p_entB,    g_entB);
    cudaGetSymbolAddress((void**)&p_usrB,    g_usrB);

    hist_both_k<<<2048, 256>>>(eidx, uidx, relw, latent);                    // #0
    scan_both_k<<<2, 1024>>>();                                              // #1
    scatter_both_k<<<2048, 256>>>(eidx, eidx + E_N, etype, uidx, iidx);      // #2

    float2* res_e = (float2*)out;
    float2* res_u = (float2*)(out + (size_t)N_ENT * DIM);

    // hop 0 (#3): base embeddings in; init residual; ZBLK tail blocks re-zero cnt
    fused_hop_k<<<EBLK + UBLK + ZBLK, 256>>>(
        (const float2*)entity_emb, (const float2*)user_emb, aggw, 0, 1,
        p_off_ent, p_packed, p_off_usr, p_items,
        (float2*)p_entB, (float2*)p_usrB, res_e, res_u);

    // hop 1 (#4): hop-0 outputs in; accumulate residual only
    fused_hop_k<<<EBLK + UBLK, 256>>>(
        (const float2*)p_entB, (const float2*)p_usrB, aggw, 1, 0,
        p_off_ent, p_packed, p_off_usr, p_items,
        nullptr, nullptr, res_e, res_u);
}